// round 1
// baseline (speedup 1.0000x reference)
#include <cuda_runtime.h>

#define B_ 2
#define S_ 4096
#define D_ 512
#define H_ 8
#define DK_ 64

// Scratch (allocation-free rule: __device__ globals, allocated at module load)
__device__ float g_q[(size_t)B_ * S_ * D_];
__device__ float g_k[(size_t)B_ * S_ * D_];
__device__ float g_v[(size_t)B_ * S_ * D_];
__device__ float g_ctx[(size_t)B_ * S_ * D_];
__device__ float g_attn[(size_t)B_ * H_ * S_ * S_];   // 1.07 GB, [B][H][Sq][Sk]

// ---------------------------------------------------------------------------
// GEMM: C[M,N] = A[M,K] @ W[N,K]^T  (both K-major), optional ReLU.
// 128x128 tile, BK=16, 256 threads, 8x8 per-thread microtile.
// ---------------------------------------------------------------------------
__global__ __launch_bounds__(256) void gemm_nt_kernel(
    const float* __restrict__ A, const float* __restrict__ W,
    float* __restrict__ C, int M, int N, int K, int relu)
{
    __shared__ float As[16][132];
    __shared__ float Bs[16][132];

    const int tid = threadIdx.x;
    const int m0 = blockIdx.y * 128;
    const int n0 = blockIdx.x * 128;
    const int ty = tid >> 4;        // 0..15  -> rows ty*8..
    const int tx = tid & 15;        // 0..15  -> cols tx*8..

    float acc[8][8];
#pragma unroll
    for (int i = 0; i < 8; i++)
#pragma unroll
        for (int j = 0; j < 8; j++) acc[i][j] = 0.0f;

    for (int k0 = 0; k0 < K; k0 += 16) {
#pragma unroll
        for (int t = 0; t < 2; t++) {
            int idx = tid + t * 256;        // 0..511
            int r = idx >> 2;               // 0..127
            int c4 = idx & 3;               // 0..3
            float4 va = *(const float4*)&A[(size_t)(m0 + r) * K + k0 + c4 * 4];
            float4 vb = *(const float4*)&W[(size_t)(n0 + r) * K + k0 + c4 * 4];
            As[c4 * 4 + 0][r] = va.x; As[c4 * 4 + 1][r] = va.y;
            As[c4 * 4 + 2][r] = va.z; As[c4 * 4 + 3][r] = va.w;
            Bs[c4 * 4 + 0][r] = vb.x; Bs[c4 * 4 + 1][r] = vb.y;
            Bs[c4 * 4 + 2][r] = vb.z; Bs[c4 * 4 + 3][r] = vb.w;
        }
        __syncthreads();
#pragma unroll
        for (int kk = 0; kk < 16; kk++) {
            float4 a0 = *(const float4*)&As[kk][ty * 8];
            float4 a1 = *(const float4*)&As[kk][ty * 8 + 4];
            float4 b0 = *(const float4*)&Bs[kk][tx * 8];
            float4 b1 = *(const float4*)&Bs[kk][tx * 8 + 4];
            float a[8] = {a0.x, a0.y, a0.z, a0.w, a1.x, a1.y, a1.z, a1.w};
            float b[8] = {b0.x, b0.y, b0.z, b0.w, b1.x, b1.y, b1.z, b1.w};
#pragma unroll
            for (int i = 0; i < 8; i++)
#pragma unroll
                for (int j = 0; j < 8; j++) acc[i][j] += a[i] * b[j];
        }
        __syncthreads();
    }

#pragma unroll
    for (int i = 0; i < 8; i++) {
        float* crow = &C[(size_t)(m0 + ty * 8 + i) * N + n0 + tx * 8];
        float4 o0, o1;
        if (relu) {
            o0 = make_float4(fmaxf(acc[i][0], 0.f), fmaxf(acc[i][1], 0.f),
                             fmaxf(acc[i][2], 0.f), fmaxf(acc[i][3], 0.f));
            o1 = make_float4(fmaxf(acc[i][4], 0.f), fmaxf(acc[i][5], 0.f),
                             fmaxf(acc[i][6], 0.f), fmaxf(acc[i][7], 0.f));
        } else {
            o0 = make_float4(acc[i][0], acc[i][1], acc[i][2], acc[i][3]);
            o1 = make_float4(acc[i][4], acc[i][5], acc[i][6], acc[i][7]);
        }
        *(float4*)&crow[0] = o0;
        *(float4*)&crow[4] = o1;
    }
}

// ---------------------------------------------------------------------------
// Phase A: scores for all 8 heads of a 64x64 (q,k) tile, kept in registers,
// then softmax over the HEADS axis (reference bug), with the exact fp32
// behavior of adding -1e9 before the /8 scaling for masked (k>q) entries:
//   fl(s - 1e9)/8 == -1.25e8 + 8*rne(s/64)   (ulp(1e9)=64, ties-to-even)
// softmax is shift-invariant, so the effective masked logit is 8*rintf(s/64).
// Writes normalized attention to g_attn[b][h][q][k].
// ---------------------------------------------------------------------------
__global__ __launch_bounds__(256) void scores_softmax_kernel(
    const float* __restrict__ q, const float* __restrict__ k,
    float* __restrict__ attn)
{
    __shared__ float qs[64 * 68];   // [d][q] transposed, pad 68
    __shared__ float ks[64 * 68];   // [d][k]

    const int tid = threadIdx.x;
    const int kt = blockIdx.x;
    const int qt = blockIdx.y;
    const int b  = blockIdx.z;
    const int qy = tid >> 4;        // 0..15 -> q rows qy*4..
    const int kx = tid & 15;        // 0..15 -> k cols kx*4..

    const float* qbase = q + (size_t)(b * S_ + qt * 64) * D_;
    const float* kbase = k + (size_t)(b * S_ + kt * 64) * D_;

    float acc[128];                 // [h][4][4], all-static indexing
#pragma unroll
    for (int i = 0; i < 128; i++) acc[i] = 0.0f;

#pragma unroll
    for (int h = 0; h < 8; h++) {
        __syncthreads();
#pragma unroll
        for (int t = 0; t < 4; t++) {
            int idx = tid + t * 256;     // 0..1023
            int r = idx >> 4;            // 0..63
            int c4 = idx & 15;           // 0..15
            float4 vq = *(const float4*)&qbase[(size_t)r * D_ + h * 64 + c4 * 4];
            float4 vk = *(const float4*)&kbase[(size_t)r * D_ + h * 64 + c4 * 4];
            qs[(c4 * 4 + 0) * 68 + r] = vq.x; qs[(c4 * 4 + 1) * 68 + r] = vq.y;
            qs[(c4 * 4 + 2) * 68 + r] = vq.z; qs[(c4 * 4 + 3) * 68 + r] = vq.w;
            ks[(c4 * 4 + 0) * 68 + r] = vk.x; ks[(c4 * 4 + 1) * 68 + r] = vk.y;
            ks[(c4 * 4 + 2) * 68 + r] = vk.z; ks[(c4 * 4 + 3) * 68 + r] = vk.w;
        }
        __syncthreads();
#pragma unroll 8
        for (int d = 0; d < 64; d++) {
            float4 a4 = *(const float4*)&qs[d * 68 + qy * 4];
            float4 b4 = *(const float4*)&ks[d * 68 + kx * 4];
            float av[4] = {a4.x, a4.y, a4.z, a4.w};
            float bv[4] = {b4.x, b4.y, b4.z, b4.w};
#pragma unroll
            for (int i = 0; i < 4; i++)
#pragma unroll
                for (int j = 0; j < 4; j++)
                    acc[h * 16 + i * 4 + j] += av[i] * bv[j];
        }
    }

    // heads-softmax + write
    const int qg0 = qt * 64 + qy * 4;
    const int kg0 = kt * 64 + kx * 4;
    const size_t bh_stride = (size_t)S_ * S_;

#pragma unroll
    for (int i = 0; i < 4; i++) {
        const int qg = qg0 + i;
        float res[8][4];
#pragma unroll
        for (int j = 0; j < 4; j++) {
            const int kg = kg0 + j;
            const bool masked = (kg > qg);
            float t[8];
#pragma unroll
            for (int h = 0; h < 8; h++) {
                float s = acc[h * 16 + i * 4 + j];
                t[h] = masked ? 8.0f * rintf(s * 0.015625f) : s * 0.125f;
            }
            float m = t[0];
#pragma unroll
            for (int h = 1; h < 8; h++) m = fmaxf(m, t[h]);
            float e[8];
            float sum = 0.0f;
#pragma unroll
            for (int h = 0; h < 8; h++) { e[h] = __expf(t[h] - m); sum += e[h]; }
            float inv = 1.0f / sum;
#pragma unroll
            for (int h = 0; h < 8; h++) res[h][j] = e[h] * inv;
        }
#pragma unroll
        for (int h = 0; h < 8; h++) {
            float4 o = make_float4(res[h][0], res[h][1], res[h][2], res[h][3]);
            *(float4*)&attn[(size_t)(b * 8 + h) * bh_stride + (size_t)qg * S_ + kg0] = o;
        }
    }
}

// ---------------------------------------------------------------------------
// Phase B: ctx[b,q,h*64+d] = sum_k attn[b,h,q,k] * v[b,k,h*64+d]
// Per (b,h): GEMM [4096 x 4096] @ [4096 x 64]. 128x64 tile, BK=32.
// ---------------------------------------------------------------------------
__global__ __launch_bounds__(256) void attn_v_kernel(
    const float* __restrict__ attn, const float* __restrict__ v,
    float* __restrict__ ctx)
{
    __shared__ float As[32 * 132];  // [k][q] transposed
    __shared__ float Vs[32 * 68];   // [k][d]

    const int tid = threadIdx.x;
    const int qt = blockIdx.x;                  // 0..31
    const int bh = blockIdx.y;                  // 0..15
    const int b = bh >> 3, h = bh & 7;

    const float* A = attn + (size_t)bh * S_ * S_ + (size_t)qt * 128 * S_;
    const float* V = v + (size_t)b * S_ * D_ + h * 64;
    float* O = ctx + (size_t)b * S_ * D_ + (size_t)qt * 128 * D_ + h * 64;

    const int ty = tid >> 4;        // rows ty*8..
    const int tx = tid & 15;        // cols tx*4..

    float acc[8][4];
#pragma unroll
    for (int i = 0; i < 8; i++)
#pragma unroll
        for (int j = 0; j < 4; j++) acc[i][j] = 0.0f;

    for (int k0 = 0; k0 < S_; k0 += 32) {
        __syncthreads();
#pragma unroll
        for (int t = 0; t < 4; t++) {
            int idx = tid + t * 256;        // 0..1023
            int r = idx >> 3;               // 0..127 (q row)
            int c4 = idx & 7;               // 0..7   (k /4)
            float4 va = *(const float4*)&A[(size_t)r * S_ + k0 + c4 * 4];
            As[(c4 * 4 + 0) * 132 + r] = va.x;
            As[(c4 * 4 + 1) * 132 + r] = va.y;
            As[(c4 * 4 + 2) * 132 + r] = va.z;
            As[(c4 * 4 + 3) * 132 + r] = va.w;
        }
#pragma unroll
        for (int t = 0; t < 2; t++) {
            int idx = tid + t * 256;        // 0..511
            int r = idx >> 4;               // 0..31  (k row)
            int c4 = idx & 15;              // 0..15  (d /4)
            float4 vv = *(const float4*)&V[(size_t)(k0 + r) * D_ + c4 * 4];
            *(float4*)&Vs[r * 68 + c4 * 4] = vv;
        }
        __syncthreads();
#pragma unroll 8
        for (int kk = 0; kk < 32; kk++) {
            float4 a0 = *(const float4*)&As[kk * 132 + ty * 8];
            float4 a1 = *(const float4*)&As[kk * 132 + ty * 8 + 4];
            float4 b4 = *(const float4*)&Vs[kk * 68 + tx * 4];
            float a[8] = {a0.x, a0.y, a0.z, a0.w, a1.x, a1.y, a1.z, a1.w};
            float bb[4] = {b4.x, b4.y, b4.z, b4.w};
#pragma unroll
            for (int i = 0; i < 8; i++)
#pragma unroll
                for (int j = 0; j < 4; j++) acc[i][j] += a[i] * bb[j];
        }
    }

#pragma unroll
    for (int i = 0; i < 8; i++) {
        float4 o = make_float4(acc[i][0], acc[i][1], acc[i][2], acc[i][3]);
        *(float4*)&O[(size_t)(ty * 8 + i) * D_ + tx * 4] = o;
    }
}

// ---------------------------------------------------------------------------
extern "C" void kernel_launch(void* const* d_in, const int* in_sizes, int n_in,
                              void* d_out, int out_size)
{
    const float* x  = (const float*)d_in[0];
    const float* Wq = (const float*)d_in[1];
    const float* Wk = (const float*)d_in[2];
    const float* Wv = (const float*)d_in[3];
    const float* Wc = (const float*)d_in[4];
    float* out = (float*)d_out;

    float *q, *k, *v, *ctx, *attn;
    cudaGetSymbolAddress((void**)&q, g_q);
    cudaGetSymbolAddress((void**)&k, g_k);
    cudaGetSymbolAddress((void**)&v, g_v);
    cudaGetSymbolAddress((void**)&ctx, g_ctx);
    cudaGetSymbolAddress((void**)&attn, g_attn);

    const int M = B_ * S_;   // 8192
    dim3 gproj(D_ / 128, M / 128);   // (4, 64)

    // Projections
    gemm_nt_kernel<<<gproj, 256>>>(x, Wq, q, M, D_, D_, 0);
    gemm_nt_kernel<<<gproj, 256>>>(x, Wk, k, M, D_, D_, 0);
    gemm_nt_kernel<<<gproj, 256>>>(x, Wv, v, M, D_, D_, 0);

    // Scores + heads-softmax -> attn
    dim3 ga(S_ / 64, S_ / 64, B_);   // (64, 64, 2)
    scores_softmax_kernel<<<ga, 256>>>(q, k, attn);

    // attn @ V -> ctx (combined-head layout)
    dim3 gb(S_ / 128, B_ * H_);      // (32, 16)
    attn_v_kernel<<<gb, 256>>>(attn, v, ctx);

    // Output projection + ReLU
    gemm_nt_kernel<<<gproj, 256>>>(ctx, Wc, out, M, D_, D_, 1);
}